// round 2
// baseline (speedup 1.0000x reference)
#include <cuda_runtime.h>

#define N_FULL   50000
#define NLAT     10
#define MU       32
#define BATCH    8
#define DEC_PAD  12
#define NODES    32
#define TMAIN    512
#define JSTRIDE  33   // padded j-stride: conflict-free for both scan writes and cnt lookups

// Scratch (static __device__ arrays: no dynamic allocation allowed)
__device__ float g_encoded[BATCH * NLAT];
__device__ __align__(16) float g_decT[N_FULL * DEC_PAD];

// ---------------------------------------------------------------------------
// Kernel 1: zero encoded accumulator + transpose decoder [n,N] -> [N,12]
// 392 blocks x 128 threads: thread per node, fully parallel.
// ---------------------------------------------------------------------------
__global__ void prep_kernel(const float* __restrict__ decoder) {
    int p = blockIdx.x * blockDim.x + threadIdx.x;
    if (blockIdx.x == 0 && threadIdx.x < BATCH * NLAT)
        g_encoded[threadIdx.x] = 0.0f;
    if (p < N_FULL) {
        float v[DEC_PAD];
#pragma unroll
        for (int i = 0; i < NLAT; i++) v[i] = decoder[(size_t)i * N_FULL + p];
        v[10] = 0.0f; v[11] = 0.0f;
        float4* dst = (float4*)(g_decT + (size_t)p * DEC_PAD);
        dst[0] = make_float4(v[0], v[1], v[2], v[3]);
        dst[1] = make_float4(v[4], v[5], v[6], v[7]);
        dst[2] = make_float4(v[8], v[9], v[10], v[11]);
    }
}

// ---------------------------------------------------------------------------
// Kernel 2: encoded[b,i] += sum_j x[b,j] * enc_w[i,j]
// 196 blocks x 256 threads. Warp w owns batch b=w; block covers a 256-idx
// window in 2 float4 rounds. ew rows are L1-broadcast across the 8 warps.
// ---------------------------------------------------------------------------
__device__ __forceinline__ float4 ld4_guard(const float* base, int idx, int n) {
    if (idx + 3 < n) return *(const float4*)(base + idx);
    float4 r = make_float4(0.f, 0.f, 0.f, 0.f);
    if (idx + 0 < n) r.x = base[idx + 0];
    if (idx + 1 < n) r.y = base[idx + 1];
    if (idx + 2 < n) r.z = base[idx + 2];
    if (idx + 3 < n) r.w = base[idx + 3];
    return r;
}

__global__ void __launch_bounds__(256)
encode_kernel(const float* __restrict__ x, const float* __restrict__ ew) {
    const int lane = threadIdx.x & 31;
    const int b    = threadIdx.x >> 5;          // warp id == batch id (8 warps)
    const int win  = blockIdx.x * 256;

    float acc[NLAT];
#pragma unroll
    for (int i = 0; i < NLAT; i++) acc[i] = 0.0f;

#pragma unroll
    for (int r = 0; r < 2; r++) {
        int idx = win + r * 128 + lane * 4;
        if (idx >= N_FULL) break;
        float4 xv = ld4_guard(x + (size_t)b * N_FULL, idx, N_FULL);
#pragma unroll
        for (int i = 0; i < NLAT; i++) {
            float4 e = ld4_guard(ew + (size_t)i * N_FULL, idx, N_FULL);
            acc[i] = fmaf(xv.x, e.x, acc[i]);
            acc[i] = fmaf(xv.y, e.y, acc[i]);
            acc[i] = fmaf(xv.z, e.z, acc[i]);
            acc[i] = fmaf(xv.w, e.w, acc[i]);
        }
    }

    float keep = 0.0f;
#pragma unroll
    for (int i = 0; i < NLAT; i++) {
        float v = acc[i];
        v += __shfl_xor_sync(0xffffffffu, v, 16);
        v += __shfl_xor_sync(0xffffffffu, v, 8);
        v += __shfl_xor_sync(0xffffffffu, v, 4);
        v += __shfl_xor_sync(0xffffffffu, v, 2);
        v += __shfl_xor_sync(0xffffffffu, v, 1);
        if (lane == i) keep = v;
    }
    if (lane < NLAT) atomicAdd(&g_encoded[b * NLAT + lane], keep);
}

// ---------------------------------------------------------------------------
// Kernel 3: main. Block = 512 threads (16 warps), 32 nodes.
//
// Gather+prefix phase (warp = 2 nodes, lane = m):
//   lane m loads neighbour m (coalesced) and its 10 decoder values (3xfloat4
//   from L2-resident g_decT), then 10 warp-inclusive-scans produce
//   Pg[i][m] and Pm2[i][m] = prefix(m^2 g), written to smem [i][m][j] with
//   j-stride 33 (scan writes hit distinct banks; cnt lookups stay ~free).
//
// Main phase (tid = ihalf*256 + b*32 + j): each thread does 5 of the 10
// latent dims; ihalf=1 parks its partial in smem, ihalf=0 combines+stores.
// Closed-form bubble window (same as R1):
//   smoothed = (Pg[cnt] - inv2*Pm2[cnt]) / (cnt - inv2*S2(cnt))
// ---------------------------------------------------------------------------
__global__ void __launch_bounds__(TMAIN, 2)
main_kernel(const float* __restrict__ enc_b,
            const float* __restrict__ bw,
            const int*   __restrict__ neigh,
            float*       __restrict__ out) {
    extern __shared__ float sm[];
    float* G  = sm;                                   // [10][32][33]
    float* W2 = sm + NLAT * MU * JSTRIDE;             // [10][32][33]
    float* P  = sm + 2 * NLAT * MU * JSTRIDE;         // [8][33] partials

    const int tid  = threadIdx.x;
    const int lane = tid & 31;          // = m in gather phase, = j in main phase
    const int warp = tid >> 5;          // 0..15
    const int p_base = blockIdx.x * NODES;

    // ---- Gather + prefix (warp handles nodes j = warp*2, warp*2+1) ----
#pragma unroll
    for (int t = 0; t < 2; t++) {
        const int jj = warp * 2 + t;
        int p = p_base + jj;
        if (p >= N_FULL) p = N_FULL - 1;              // clamp: results unused
        const int nb = neigh[(size_t)p * MU + lane];  // coalesced across lanes
        const float4* src = (const float4*)(g_decT + (size_t)nb * DEC_PAD);
        float4 a = src[0], b4 = src[1], c4 = src[2];
        float g[NLAT] = {a.x, a.y, a.z, a.w, b4.x, b4.y, b4.z, b4.w, c4.x, c4.y};
        const float m2 = (float)(lane * lane);
#pragma unroll
        for (int i = 0; i < NLAT; i++) {
            float s  = g[i];
            float t2 = m2 * g[i];
#pragma unroll
            for (int d = 1; d < 32; d <<= 1) {
                float as = __shfl_up_sync(0xffffffffu, s,  d);
                float at = __shfl_up_sync(0xffffffffu, t2, d);
                if (lane >= d) { s += as; t2 += at; }
            }
            G [(i * MU + lane) * JSTRIDE + jj] = s;
            W2[(i * MU + lane) * JSTRIDE + jj] = t2;
        }
    }
    __syncthreads();

    // ---- Main phase ----
    const int ihalf = tid >> 8;         // 0 or 1
    const int b     = (tid >> 5) & 7;
    const int j     = lane;
    const int p     = p_base + j;
    const int pc    = (p < N_FULL) ? p : (N_FULL - 1);

    float encb[NLAT];
#pragma unroll
    for (int k = 0; k < NLAT; k++)
        encb[k] = g_encoded[b * NLAT + k] + enc_b[k];

    float acc = 0.0f;
#pragma unroll
    for (int ii = 0; ii < 5; ii++) {
        const int i = ihalf * 5 + ii;
        float z = 0.0f;
#pragma unroll
        for (int k = 0; k < NLAT; k++)
            z = fmaf(encb[k], bw[((size_t)(i * NLAT + k)) * N_FULL + pc], z);

        float e  = __expf(-z);
        float tt = 1.0f + e;                              // = 1/w
        float u  = __fdividef((float)MU, tt);             // = MU*w
        int cnt  = min(MU, (int)u + 1);
        float inv2 = tt * tt * (1.0f / (float)(MU * MU)); // 1/(MU*w)^2

        float Pg = G [(i * MU + (cnt - 1)) * JSTRIDE + j];
        float Pm = W2[(i * MU + (cnt - 1)) * JSTRIDE + j];
        int   c1 = cnt - 1;
        float S2 = (float)(c1 * cnt * (2 * cnt - 1)) * (1.0f / 6.0f);
        float s  = (float)cnt - inv2 * S2;
        float smv = __fdividef(fmaf(-inv2, Pm, Pg), s);
        acc = fmaf(encb[i], smv, acc);
    }

    if (ihalf == 1) P[b * JSTRIDE + j] = acc;
    __syncthreads();
    if (ihalf == 0 && p < N_FULL)
        out[(size_t)b * N_FULL + p] = acc + P[b * JSTRIDE + j];
}

// ---------------------------------------------------------------------------
extern "C" void kernel_launch(void* const* d_in, const int* in_sizes, int n_in,
                              void* d_out, int out_size) {
    const float* x       = (const float*)d_in[0];
    const float* enc_w   = (const float*)d_in[1];
    const float* enc_b   = (const float*)d_in[2];
    const float* decoder = (const float*)d_in[3];
    const float* bw      = (const float*)d_in[4];
    const int*   neigh   = (const int*)  d_in[5];
    float*       out     = (float*)d_out;
    (void)in_sizes; (void)n_in; (void)out_size;

    prep_kernel<<<392, 128>>>(decoder);
    encode_kernel<<<196, 256>>>(x, enc_w);

    size_t smem_bytes = (size_t)(2 * NLAT * MU * JSTRIDE + BATCH * JSTRIDE)
                        * sizeof(float);   // 85,536 B
    cudaFuncSetAttribute(main_kernel,
                         cudaFuncAttributeMaxDynamicSharedMemorySize,
                         (int)smem_bytes);
    main_kernel<<<(N_FULL + NODES - 1) / NODES, TMAIN, smem_bytes>>>(
        enc_b, bw, neigh, out);
}

// round 3
// speedup vs baseline: 1.1090x; 1.1090x over previous
#include <cuda_runtime.h>

#define N_FULL   50000
#define NLAT     10
#define MU       32
#define BATCH    8
#define NODES    32
#define ROWPAD   16      // floats per padded decoder row (64 bytes)
#define MSTR     33      // m-stride in G/W2 (padded)
#define ISTR     1058    // i-stride = 32*33 + 2  (ISTR mod 32 == 2 -> bank has 2i term)
#define GSZ      (NLAT * ISTR)   // 10580 floats per array

// Scratch (static __device__ arrays: no dynamic allocation allowed)
__device__ float g_encoded[BATCH * NLAT];
__device__ __align__(128) float g_dec4[N_FULL * ROWPAD];   // 3.2 MB, 64B rows

// ---------------------------------------------------------------------------
// Kernel 1 (fused): blocks 0..79 compute encoded[b,i] directly (no atomics,
// no zero-init; x/ew stay L2-resident across the 80 blocks). Blocks 80..275
// transpose decoder [n,N] -> [N,16] with 64B-aligned rows.
// ---------------------------------------------------------------------------
__global__ void __launch_bounds__(256)
prep_encode_kernel(const float* __restrict__ x,
                   const float* __restrict__ ew,
                   const float* __restrict__ decoder) {
    if (blockIdx.x < BATCH * NLAT) {
        const int b = blockIdx.x / NLAT;
        const int i = blockIdx.x % NLAT;
        const float4* xr = (const float4*)(x  + (size_t)b * N_FULL);
        const float4* wr = (const float4*)(ew + (size_t)i * N_FULL);
        float acc = 0.0f;
        for (int t = threadIdx.x; t < N_FULL / 4; t += 256) {
            float4 a = __ldg(xr + t);
            float4 c = __ldg(wr + t);
            acc = fmaf(a.x, c.x, acc);
            acc = fmaf(a.y, c.y, acc);
            acc = fmaf(a.z, c.z, acc);
            acc = fmaf(a.w, c.w, acc);
        }
#pragma unroll
        for (int d = 16; d > 0; d >>= 1)
            acc += __shfl_xor_sync(0xffffffffu, acc, d);
        __shared__ float red[8];
        int lane = threadIdx.x & 31, warp = threadIdx.x >> 5;
        if (lane == 0) red[warp] = acc;
        __syncthreads();
        if (threadIdx.x == 0) {
            float s = 0.0f;
#pragma unroll
            for (int w = 0; w < 8; w++) s += red[w];
            g_encoded[blockIdx.x] = s;
        }
    } else {
        int p = (blockIdx.x - BATCH * NLAT) * 256 + threadIdx.x;
        if (p < N_FULL) {
            float v[NLAT];
#pragma unroll
            for (int i = 0; i < NLAT; i++) v[i] = __ldg(decoder + (size_t)i * N_FULL + p);
            float4* dst = (float4*)(g_dec4 + (size_t)p * ROWPAD);
            dst[0] = make_float4(v[0], v[1], v[2], v[3]);
            dst[1] = make_float4(v[4], v[5], v[6], v[7]);
            dst[2] = make_float4(v[8], v[9], 0.0f, 0.0f);
            dst[3] = make_float4(0.0f, 0.0f, 0.0f, 0.0f);
        }
    }
}

// ---------------------------------------------------------------------------
// Kernel 2: main. Block = 256 threads (8 warps), 32 nodes.
//
// Phase A (gather, cooperative): 1024 rows/block. 4 lanes share one 64B row
//   (lane quarter q = lane&3 loads one float4) -> one warp LDG.128 fetches 8
//   full rows coalesced into 8 line-touches: 1 L1 wavefront per row (3x fewer
//   than per-lane row loads). Values scattered to smem G[i][m][j]; with
//   ISTR=1058 the bank is (8q+2u+m+j)%32: conflict-free.
// Phase B (scan): task (i,j) serially prefixes over m in smem:
//   G <- prefix(g), W2 <- prefix(m^2 g). Banks (2i+m+j)%32: conflict-free.
// Phase C: thread = (b=warp, j=lane), all 10 latent dims. Closed-form bubble
//   window: smoothed = (Pg[cnt-1] - inv2*Pm2[cnt-1]) / (cnt - inv2*S2(cnt)).
// ---------------------------------------------------------------------------
__global__ void __launch_bounds__(256, 2)
main_kernel(const float* __restrict__ enc_b,
            const float* __restrict__ bw,
            const int*   __restrict__ neigh,
            float*       __restrict__ out) {
    extern __shared__ float sm[];
    float* G  = sm;             // [GSZ]
    float* W2 = sm + GSZ;       // [GSZ]
    int*   NB = (int*)(sm + 2 * GSZ);   // [1024] flat: NB[j*32+m]

    const int tid    = threadIdx.x;
    const int lane   = tid & 31;
    const int warp   = tid >> 5;
    const int p_base = blockIdx.x * NODES;

    // ---- load neighbour tile (flat, coalesced int4) ----
    {
        int base = p_base * MU + tid * 4;
        int4 v = make_int4(0, 0, 0, 0);
        if (base < N_FULL * MU) v = *(const int4*)(neigh + base);
        NB[tid * 4 + 0] = v.x;
        NB[tid * 4 + 1] = v.y;
        NB[tid * 4 + 2] = v.z;
        NB[tid * 4 + 3] = v.w;
    }
    __syncthreads();

    // ---- Phase A: cooperative gather (128 rows per warp, 8 rows/round) ----
    {
        const int q  = lane & 3;        // row quarter
        const int rl = lane >> 2;       // row-in-round 0..7
        const int wbase = warp * 128;
#pragma unroll 8
        for (int t = 0; t < 16; t++) {
            const int r  = wbase + t * 8 + rl;   // flat row index
            const int j  = r >> 5;
            const int m  = r & 31;
            const int nb = NB[r];
            float4 v = __ldg((const float4*)(g_dec4 + (size_t)nb * ROWPAD) + q);
            const int a0 = (4 * q) * ISTR + m * MSTR + j;
            if (q < 2) {
                G[a0          ] = v.x;
                G[a0 + ISTR   ] = v.y;
                G[a0 + 2*ISTR ] = v.z;
                G[a0 + 3*ISTR ] = v.w;
            } else if (q == 2) {
                G[a0          ] = v.x;   // i = 8
                G[a0 + ISTR   ] = v.y;   // i = 9
            }
        }
    }
    __syncthreads();

    // ---- Phase B: inclusive prefix over m ----
    for (int task = tid; task < NLAT * NODES; task += 256) {
        const int i = task >> 5;
        const int j = task & 31;
        const int base = i * ISTR + j;
        float pg = 0.0f, pm = 0.0f;
#pragma unroll
        for (int m = 0; m < MU; m++) {
            float v = G[base + m * MSTR];
            pg += v;
            pm = fmaf((float)(m * m), v, pm);
            G [base + m * MSTR] = pg;
            W2[base + m * MSTR] = pm;
        }
    }
    __syncthreads();

    // ---- Phase C: thread = (b = warp, node j = lane) ----
    const int b = warp, j = lane;
    const int p  = p_base + j;
    const int pc = (p < N_FULL) ? p : (N_FULL - 1);

    float encb[NLAT];
#pragma unroll
    for (int k = 0; k < NLAT; k++)
        encb[k] = g_encoded[b * NLAT + k] + __ldg(enc_b + k);

    float acc = 0.0f;
#pragma unroll
    for (int i = 0; i < NLAT; i++) {
        float z = 0.0f;
#pragma unroll
        for (int k = 0; k < NLAT; k++)
            z = fmaf(encb[k], __ldg(bw + ((size_t)(i * NLAT + k)) * N_FULL + pc), z);

        float e    = __expf(-z);
        float tt   = 1.0f + e;                              // = 1/w
        float u    = __fdividef((float)MU, tt);             // = MU*w
        int   cnt  = min(MU, (int)u + 1);                   // #active m
        float inv2 = tt * tt * (1.0f / (float)(MU * MU));   // 1/(MU*w)^2

        const int base = i * ISTR + (cnt - 1) * MSTR + j;
        float Pg = G[base];
        float Pm = W2[base];
        int   c1 = cnt - 1;
        float S2 = (float)(c1 * cnt * (2 * cnt - 1)) * (1.0f / 6.0f);
        float s  = (float)cnt - inv2 * S2;
        float smv = __fdividef(fmaf(-inv2, Pm, Pg), s);
        acc = fmaf(encb[i], smv, acc);
    }
    if (p < N_FULL)
        out[(size_t)b * N_FULL + p] = acc;
}

// ---------------------------------------------------------------------------
extern "C" void kernel_launch(void* const* d_in, const int* in_sizes, int n_in,
                              void* d_out, int out_size) {
    const float* x       = (const float*)d_in[0];
    const float* enc_w   = (const float*)d_in[1];
    const float* enc_b   = (const float*)d_in[2];
    const float* decoder = (const float*)d_in[3];
    const float* bw      = (const float*)d_in[4];
    const int*   neigh   = (const int*)  d_in[5];
    float*       out     = (float*)d_out;
    (void)in_sizes; (void)n_in; (void)out_size;

    const int tp_blocks = (N_FULL + 255) / 256;                 // 196
    prep_encode_kernel<<<BATCH * NLAT + tp_blocks, 256>>>(x, enc_w, decoder);

    size_t smem_bytes = (size_t)(2 * GSZ) * sizeof(float)
                      + (size_t)(NODES * MU) * sizeof(int);     // 88,736 B
    cudaFuncSetAttribute(main_kernel,
                         cudaFuncAttributeMaxDynamicSharedMemorySize,
                         (int)smem_bytes);
    main_kernel<<<(N_FULL + NODES - 1) / NODES, 256, smem_bytes>>>(
        enc_b, bw, neigh, out);
}

// round 4
// speedup vs baseline: 1.3597x; 1.2260x over previous
#include <cuda_runtime.h>

#define N_FULL   50000
#define NLAT     10
#define NLAT_H   5       // latent dims per pass
#define MU       32
#define BATCH    8
#define NODES    32
#define MSTR     33      // m-stride in G/W2 (padded)
#define ISTR     1058    // i-stride = 32*33 + 2  (mod 32 == 2 -> bank gets 2i term)
#define GSZ      (NLAT_H * ISTR)   // 5290 floats per array

// Scratch (static __device__ arrays: no dynamic allocation allowed)
__device__ float g_encoded[BATCH * NLAT];
__device__ __align__(128) float g_decA[N_FULL * 8];   // rows: [i0..i4, pad x3], 32B
__device__ __align__(128) float g_decB[N_FULL * 8];   // rows: [i5..i9, pad x3], 32B

// ---------------------------------------------------------------------------
// Kernel 1 (fused): blocks 0..79 compute encoded[b,i] directly (no atomics,
// no zero-init). Blocks 80..275 transpose decoder [n,N] into the two 32B-row
// half-tables decA (i0..4) / decB (i5..9).
// ---------------------------------------------------------------------------
__global__ void __launch_bounds__(256)
prep_encode_kernel(const float* __restrict__ x,
                   const float* __restrict__ ew,
                   const float* __restrict__ decoder) {
    if (blockIdx.x < BATCH * NLAT) {
        const int b = blockIdx.x / NLAT;
        const int i = blockIdx.x % NLAT;
        const float4* xr = (const float4*)(x  + (size_t)b * N_FULL);
        const float4* wr = (const float4*)(ew + (size_t)i * N_FULL);
        float acc = 0.0f;
        for (int t = threadIdx.x; t < N_FULL / 4; t += 256) {
            float4 a = __ldg(xr + t);
            float4 c = __ldg(wr + t);
            acc = fmaf(a.x, c.x, acc);
            acc = fmaf(a.y, c.y, acc);
            acc = fmaf(a.z, c.z, acc);
            acc = fmaf(a.w, c.w, acc);
        }
#pragma unroll
        for (int d = 16; d > 0; d >>= 1)
            acc += __shfl_xor_sync(0xffffffffu, acc, d);
        __shared__ float red[8];
        int lane = threadIdx.x & 31, warp = threadIdx.x >> 5;
        if (lane == 0) red[warp] = acc;
        __syncthreads();
        if (threadIdx.x == 0) {
            float s = 0.0f;
#pragma unroll
            for (int w = 0; w < 8; w++) s += red[w];
            g_encoded[blockIdx.x] = s;
        }
    } else {
        int p = (blockIdx.x - BATCH * NLAT) * 256 + threadIdx.x;
        if (p < N_FULL) {
            float v[NLAT];
#pragma unroll
            for (int i = 0; i < NLAT; i++)
                v[i] = __ldg(decoder + (size_t)i * N_FULL + p);
            float4* dA = (float4*)(g_decA + (size_t)p * 8);
            float4* dB = (float4*)(g_decB + (size_t)p * 8);
            dA[0] = make_float4(v[0], v[1], v[2], v[3]);
            dA[1] = make_float4(v[4], 0.0f, 0.0f, 0.0f);
            dB[0] = make_float4(v[5], v[6], v[7], v[8]);
            dB[1] = make_float4(v[9], 0.0f, 0.0f, 0.0f);
        }
    }
}

// ---------------------------------------------------------------------------
// Kernel 2: main. Block = 256 threads (8 warps), 32 nodes, TWO i-passes of 5.
//
// Per pass:
//  Phase A (gather): 2 lanes share one 32B decoder half-row (lane q=lane&1
//    loads one float4) -> warp LDG covers 16 rows = 16 line-touches: 1
//    wavefront/row, and only 2 touches/row across both passes (was 3).
//    Scatter to smem G[ii][m][j]; bank = (2*ii + m + j)%32, conflict-free.
//  Phase B (scan): task (ii,j) = one thread (160 tasks, single round):
//    G <- prefix(g), W2 <- prefix(m^2 g) over m. Conflict-free.
//  Phase C: thread = (b=warp, j=lane), 5 latent dims accumulated into acc.
//    Closed-form bubble window:
//      smoothed = (Pg[cnt-1] - inv2*Pm2[cnt-1]) / (cnt - inv2*S2(cnt)).
// Static smem 46.4KB + launch_bounds(256,4) -> 4 CTAs/SM (32 warps).
// ---------------------------------------------------------------------------
__global__ void __launch_bounds__(256, 4)
main_kernel(const float* __restrict__ enc_b,
            const float* __restrict__ bw,
            const int*   __restrict__ neigh,
            float*       __restrict__ out) {
    __shared__ float G[GSZ];
    __shared__ float W2[GSZ];
    __shared__ int   NB[NODES * MU];

    const int tid    = threadIdx.x;
    const int lane   = tid & 31;
    const int warp   = tid >> 5;
    const int p_base = blockIdx.x * NODES;

    // ---- load neighbour tile (flat, coalesced int4) ----
    {
        int base = p_base * MU + tid * 4;
        int4 v = make_int4(0, 0, 0, 0);
        if (base < N_FULL * MU) v = *(const int4*)(neigh + base);
        NB[tid * 4 + 0] = v.x;
        NB[tid * 4 + 1] = v.y;
        NB[tid * 4 + 2] = v.z;
        NB[tid * 4 + 3] = v.w;
    }

    // ---- per-thread constants for phase C ----
    const int b  = warp;           // batch
    const int j  = lane;           // node within tile
    const int p  = p_base + j;
    const int pc = (p < N_FULL) ? p : (N_FULL - 1);

    float encb[NLAT];
#pragma unroll
    for (int k = 0; k < NLAT; k++)
        encb[k] = g_encoded[b * NLAT + k] + __ldg(enc_b + k);

    float acc = 0.0f;

    __syncthreads();

#pragma unroll
    for (int pass = 0; pass < 2; pass++) {
        const float4* dec = (const float4*)(pass ? g_decB : g_decA);

        // ---- Phase A: cooperative gather ----
        {
            const int q  = lane & 1;       // half-row quarter (16B)
            const int rl = lane >> 1;      // row-in-round 0..15
#pragma unroll 4
            for (int t = 0; t < 8; t++) {
                const int r  = warp * 128 + t * 16 + rl;  // flat row index
                const int jm = r & 31;                    // m
                const int jj = r >> 5;                    // node j
                const int nb = NB[r];
                float4 v = __ldg(dec + nb * 2 + q);
                const int a0 = jm * MSTR + jj;
                if (q == 0) {
                    G[a0           ] = v.x;
                    G[a0 +     ISTR] = v.y;
                    G[a0 + 2 * ISTR] = v.z;
                    G[a0 + 3 * ISTR] = v.w;
                } else {
                    G[a0 + 4 * ISTR] = v.x;
                }
            }
        }
        __syncthreads();

        // ---- Phase B: inclusive prefix over m (160 tasks, one round) ----
        if (tid < NLAT_H * NODES) {
            const int ii = tid >> 5;
            const int jj = tid & 31;
            const int base = ii * ISTR + jj;
            float pg = 0.0f, pm = 0.0f;
#pragma unroll
            for (int m = 0; m < MU; m++) {
                float v = G[base + m * MSTR];
                pg += v;
                pm = fmaf((float)(m * m), v, pm);
                G [base + m * MSTR] = pg;
                W2[base + m * MSTR] = pm;
            }
        }
        __syncthreads();

        // ---- Phase C: 5 latent dims for (b, p) ----
#pragma unroll
        for (int ii = 0; ii < NLAT_H; ii++) {
            const int i = pass * NLAT_H + ii;
            float z = 0.0f;
#pragma unroll
            for (int k = 0; k < NLAT; k++)
                z = fmaf(encb[k],
                         __ldg(bw + ((size_t)(i * NLAT + k)) * N_FULL + pc), z);

            float e    = __expf(-z);
            float tt   = 1.0f + e;                              // = 1/w
            float u    = __fdividef((float)MU, tt);             // = MU*w
            int   cnt  = min(MU, (int)u + 1);                   // #active m
            float inv2 = tt * tt * (1.0f / (float)(MU * MU));   // 1/(MU*w)^2

            const int base = ii * ISTR + (cnt - 1) * MSTR + j;
            float Pg = G[base];
            float Pm = W2[base];
            int   c1 = cnt - 1;
            float S2 = (float)(c1 * cnt * (2 * cnt - 1)) * (1.0f / 6.0f);
            float s  = (float)cnt - inv2 * S2;
            float smv = __fdividef(fmaf(-inv2, Pm, Pg), s);
            acc = fmaf(encb[i], smv, acc);
        }
        if (pass == 0) __syncthreads();   // protect G/W2 before pass-2 gather
    }

    if (p < N_FULL)
        out[(size_t)b * N_FULL + p] = acc;
}

// ---------------------------------------------------------------------------
extern "C" void kernel_launch(void* const* d_in, const int* in_sizes, int n_in,
                              void* d_out, int out_size) {
    const float* x       = (const float*)d_in[0];
    const float* enc_w   = (const float*)d_in[1];
    const float* enc_b   = (const float*)d_in[2];
    const float* decoder = (const float*)d_in[3];
    const float* bw      = (const float*)d_in[4];
    const int*   neigh   = (const int*)  d_in[5];
    float*       out     = (float*)d_out;
    (void)in_sizes; (void)n_in; (void)out_size;

    const int tp_blocks = (N_FULL + 255) / 256;                 // 196
    prep_encode_kernel<<<BATCH * NLAT + tp_blocks, 256>>>(x, enc_w, decoder);

    main_kernel<<<(N_FULL + NODES - 1) / NODES, 256>>>(enc_b, bw, neigh, out);
}